// round 16
// baseline (speedup 1.0000x reference)
#include <cuda_runtime.h>
#include <cuda_fp16.h>
#include <cstdint>
#include <math.h>

#define NTHR 256
#define NTILES 4096                  // 64 pixels per tile, 2 tile-streams per CTA
#define OUT_PIX (16*128*128*3)

// ---- smem byte offsets ----
#define OFF_RING(g) ((g)*40960)          // 2 stages x 20480 per group
#define OFF_A(g)   (81920 + (g)*32768)   // A: [64 m][256 k] fp16, 512B rows, swizzled
#define OFF_W1A 147456
#define OFF_W1B 148480
#define OFF_B1  149504
#define OFF_B2  150528
#define OFF_B3  151552
#define OFF_W4  152576                   // float[768]
#define OFF_PART(g) (155648 + (g)*3072)  // float[4][64][3] per group
#define OFF_MB  161792                   // per group 32B: F0,F1,U0,U1
#define OFF_TOK(g) (161856 + (g)*8)      // MMA ownership tokens
#define SMEM_ALLOC 161920

// fp16 weight images: [layer][kchunk(8 x k32)][256 n x 80B rows]
__device__ __align__(16) unsigned char g_W[2][8][20480];

// ---- helpers ----
__device__ __forceinline__ uint32_t smem_u32(const void* p) {
    uint32_t a;
    asm("{ .reg .u64 t; cvta.to.shared.u64 t, %1; cvt.u32.u64 %0, t; }" : "=r"(a) : "l"(p));
    return a;
}
#define GBAR(id) asm volatile("bar.sync %0, 128;" :: "r"(id) : "memory")
#define MBAR_INIT(mbar, cnt) \
    asm volatile("mbarrier.init.shared.b64 [%0], %1;" :: "r"((uint32_t)(mbar)), "r"((uint32_t)(cnt)) : "memory")
#define MBAR_EXPECT_TX(mbar, tx) \
    asm volatile("mbarrier.arrive.expect_tx.shared.b64 _, [%0], %1;" :: "r"((uint32_t)(mbar)), "r"((uint32_t)(tx)) : "memory")
#define MBAR_ARRIVE(mbar) \
    asm volatile("mbarrier.arrive.shared.b64 _, [%0];" :: "r"((uint32_t)(mbar)) : "memory")

__device__ __forceinline__ void mbar_wait(uint32_t mbar, uint32_t parity) {
    uint32_t done;
    asm volatile("{\n\t.reg .pred p;\n\t"
                 "mbarrier.try_wait.parity.acquire.cta.shared::cta.b64 p, [%1], %2;\n\t"
                 "selp.b32 %0, 1, 0, p;\n\t}" : "=r"(done) : "r"(mbar), "r"(parity) : "memory");
    if (!done) {
        asm volatile("{\n\t.reg .pred P1;\n\t"
                     "W_%=:\n\t"
                     "mbarrier.try_wait.parity.acquire.cta.shared::cta.b64 P1, [%0], %1, 0x989680;\n\t"
                     "@P1 bra.uni D_%=;\n\t"
                     "bra.uni W_%=;\n\t"
                     "D_%=:\n\t}" :: "r"(mbar), "r"(parity) : "memory");
    }
}
__device__ __forceinline__ void bulk_ld(uint32_t dst, const void* src, uint32_t bytes, uint32_t mbar) {
    asm volatile("cp.async.bulk.shared::cluster.global.mbarrier::complete_tx::bytes [%0], [%1], %2, [%3];"
                 :: "r"(dst), "l"(src), "r"(bytes), "r"(mbar) : "memory");
}
#define LDSM4(r, addr) \
    asm volatile("ldmatrix.sync.aligned.m8n8.x4.shared.b16 {%0,%1,%2,%3}, [%4];" \
        : "=r"((r)[0]), "=r"((r)[1]), "=r"((r)[2]), "=r"((r)[3]) : "r"(addr))
#define MMA4(dd, a, b0_, b1_) \
    asm volatile("mma.sync.aligned.m16n8k16.row.col.f32.f16.f16.f32 " \
        "{%0,%1,%2,%3}, {%4,%5,%6,%7}, {%8,%9}, {%0,%1,%2,%3};" \
        : "+f"((dd)[0]), "+f"((dd)[1]), "+f"((dd)[2]), "+f"((dd)[3]) \
        : "r"((a)[0]), "r"((a)[1]), "r"((a)[2]), "r"((a)[3]), "r"(b0_), "r"(b1_))

// A smem address within a group's A buffer: [m][k] fp16, 512B rows, chunk XOR swizzle
__device__ __forceinline__ uint32_t a_addr(uint32_t base, int m, int k) {
    return base + (uint32_t)(m * 512) +
           (uint32_t)(((((k >> 3) ^ (m & 7))) << 4) + ((k & 7) << 1));
}
__device__ __forceinline__ void store_h2(unsigned char* sm, uint32_t abase, int m, int n, float v0, float v1) {
    *(__half2*)(sm + a_addr(abase, m, n)) = __float22half2_rn(make_float2(v0, v1));
}

// ---- prep: W2/W3 fp16 images, [n][k] layout, 80B rows ----
__global__ void prep_kernel(const float* __restrict__ W2, const float* __restrict__ W3) {
    int idx = blockIdx.x * blockDim.x + threadIdx.x;   // 0..131071
    int l = idx >> 16, r = idx & 65535;
    int k = r >> 8, n = r & 255;
    float w = (l ? W3 : W2)[k * 256 + n];
    __half h = __float2half_rn(w);
    int kc = k >> 5, kk = k & 31;
    *(__half*)&g_W[l][kc][n * 80 + kk * 2] = h;
}

// group ring: F(s) at mb, U(s) at mb+16
__device__ __forceinline__ void issue_load(uint32_t smb, uint32_t ring, uint32_t mb, int g) {
    const int l = (g >> 3) & 1, kc = g & 7, s = g & 1;
    MBAR_EXPECT_TX(smb + mb + s * 8, 20480);
    bulk_ld(smb + ring + s * 20480, &g_W[l][kc][0], 20480, smb + mb + s * 8);
}

// one 256->256 layer for a 64-px group tile: 4 warps, warp tile 64x64 (m0=0)
__device__ __forceinline__ void run_layer(
    float (&d)[4][8][4], uint32_t smb, uint32_t ring, uint32_t abase, uint32_t mb,
    int n0, int lane, int gtid, int& g, int total_chunks)
{
    const int aRow = (lane & 7) + ((lane >> 3) & 1) * 8;
    const int aCs  = lane >> 4;
    const int wRow = ((lane >> 4) & 1) * 8 + (lane & 7);
    const int wCs  = (lane >> 3) & 1;

    for (int kc = 0; kc < 8; kc++) {
        const int s = g & 1;
        const uint32_t ph = (uint32_t)((g >> 1) & 1);
        mbar_wait(smb + mb + s * 8, ph);                   // F[s]
        const uint32_t stH = smb + ring + s * 20480;
#pragma unroll
        for (int ks = 0; ks < 2; ks++) {
            const int cb = kc * 4 + ks * 2 + aCs;
            uint32_t ah[4][4];
#pragma unroll
            for (int mt = 0; mt < 4; mt++) {
                const int mA = mt * 16 + aRow;
                const uint32_t co = (uint32_t)((cb ^ (mA & 7)) << 4);
                LDSM4(ah[mt], smb + abase + (uint32_t)(mA * 512) + co);
            }
            const uint32_t wko = (uint32_t)((ks * 2 + wCs) << 4);
#pragma unroll
            for (int np = 0; np < 4; np++) {
                const uint32_t wro = (uint32_t)((n0 + np * 16 + wRow) * 80) + wko;
                uint32_t wh[4];
                LDSM4(wh, stH + wro);
#pragma unroll
                for (int mt = 0; mt < 4; mt++) {
                    MMA4(d[mt][np*2],   ah[mt], wh[0], wh[1]);
                    MMA4(d[mt][np*2+1], ah[mt], wh[2], wh[3]);
                }
            }
        }
        if (lane == 0) MBAR_ARRIVE(smb + mb + 16 + s * 8); // U[s], count 4
        if (gtid == 0 && g + 2 < total_chunks) {
            mbar_wait(smb + mb + 16 + s * 8, ph);          // stage drained by group
            issue_load(smb, ring, mb, g + 2);
        }
        g++;
    }
}

// layer-2 epilogue: bias+relu, fp16 store back to the group's A buffer
__device__ __forceinline__ void epi_store(
    unsigned char* sm, uint32_t abase, float (&d)[4][8][4], const float* bias,
    int n0, int qm, int qn)
{
#pragma unroll
    for (int mt = 0; mt < 4; mt++) {
        const int mA = mt * 16 + qm;
#pragma unroll
        for (int nt = 0; nt < 8; nt++) {
            const int n = n0 + nt * 8 + qn;
            const float bb0 = bias[n], bb1 = bias[n + 1];
            store_h2(sm, abase, mA,     n, fmaxf(d[mt][nt][0] + bb0, 0.f), fmaxf(d[mt][nt][1] + bb1, 0.f));
            store_h2(sm, abase, mA + 8, n, fmaxf(d[mt][nt][2] + bb0, 0.f), fmaxf(d[mt][nt][3] + bb1, 0.f));
        }
    }
}

// layer-3 epilogue fused with layer-4 from fragments
__device__ __forceinline__ void epi3_fuse(
    float (&d)[4][8][4], const float* b3v, const float* w4s, float* part,
    int n0, int gwid, int lane, int qm, int qn)
{
#pragma unroll
    for (int mt = 0; mt < 4; mt++) {
        float oo[2][3];
#pragma unroll
        for (int h = 0; h < 2; h++)
#pragma unroll
            for (int j = 0; j < 3; j++) oo[h][j] = 0.f;
#pragma unroll
        for (int nt = 0; nt < 8; nt++) {
            const int n = n0 + nt * 8 + qn;
            const float2 bb = *(const float2*)&b3v[n];
            const float2 wA = *(const float2*)&w4s[n * 3];
            const float2 wB = *(const float2*)&w4s[n * 3 + 2];
            const float2 wC = *(const float2*)&w4s[n * 3 + 4];
            float v0 = fmaxf(d[mt][nt][0] + bb.x, 0.f);
            float v1 = fmaxf(d[mt][nt][1] + bb.y, 0.f);
            float v2 = fmaxf(d[mt][nt][2] + bb.x, 0.f);
            float v3 = fmaxf(d[mt][nt][3] + bb.y, 0.f);
            oo[0][0] = fmaf(v0, wA.x, fmaf(v1, wB.y, oo[0][0]));
            oo[0][1] = fmaf(v0, wA.y, fmaf(v1, wC.x, oo[0][1]));
            oo[0][2] = fmaf(v0, wB.x, fmaf(v1, wC.y, oo[0][2]));
            oo[1][0] = fmaf(v2, wA.x, fmaf(v3, wB.y, oo[1][0]));
            oo[1][1] = fmaf(v2, wA.y, fmaf(v3, wC.x, oo[1][1]));
            oo[1][2] = fmaf(v2, wB.x, fmaf(v3, wC.y, oo[1][2]));
        }
#pragma unroll
        for (int h = 0; h < 2; h++)
#pragma unroll
            for (int j = 0; j < 3; j++) {
                float v = oo[h][j];
                v += __shfl_xor_sync(0xFFFFFFFFu, v, 1);
                v += __shfl_xor_sync(0xFFFFFFFFu, v, 2);
                oo[h][j] = v;
            }
        if ((lane & 3) == 0) {
#pragma unroll
            for (int h = 0; h < 2; h++) {
                const int row = mt * 16 + h * 8 + qm;
#pragma unroll
                for (int j = 0; j < 3; j++)
                    part[gwid * 192 + row * 3 + j] = oo[h][j];
            }
        }
    }
}

#define ZERO_D(d) do { \
_Pragma("unroll") for (int i = 0; i < 4; i++) \
_Pragma("unroll") for (int j = 0; j < 8; j++) \
_Pragma("unroll") for (int kq = 0; kq < 4; kq++) (d)[i][j][kq] = 0.f; } while (0)

__global__ void __launch_bounds__(NTHR, 1) inr_hmma_kernel(
    const float* __restrict__ x, const int* __restrict__ sample_idx,
    const float* __restrict__ shiftv, const float* __restrict__ rotang,
    const float* __restrict__ cscal, const float* __restrict__ cshft,
    const float* __restrict__ W1, const float* __restrict__ b1,
    const float* __restrict__ b2, const float* __restrict__ b3,
    const float* __restrict__ W4, const float* __restrict__ b4,
    float* __restrict__ out)
{
    extern __shared__ __align__(128) unsigned char sm[];
    const uint32_t smb = smem_u32(sm);

    const int tid = threadIdx.x;
    const int lane = tid & 31, wid = tid >> 5;
    const int gid = wid >> 2;                 // warp group 0/1
    const int gwid = wid & 3;                 // warp within group
    const int gtid = tid & 127;
    const int bar = 1 + gid;                  // named barrier id
    const int n0 = gwid * 64;                 // warp tile 64x64, m0 = 0
    const int qm = lane >> 2, qn = (lane & 3) * 2;

    const uint32_t ring  = OFF_RING(gid);
    const uint32_t abase = OFF_A(gid);
    const uint32_t mb    = OFF_MB + gid * 32;
    const uint32_t tokMine  = smb + OFF_TOK(gid);
    const uint32_t tokOther = smb + OFF_TOK(1 - gid);

    float* w1a = (float*)(sm + OFF_W1A);
    float* w1b = (float*)(sm + OFF_W1B);
    float* b1v = (float*)(sm + OFF_B1);
    float* b2v = (float*)(sm + OFF_B2);
    float* b3v = (float*)(sm + OFF_B3);
    float* w4s = (float*)(sm + OFF_W4);
    float* part = (float*)(sm + OFF_PART(gid));

    w1a[tid] = W1[tid]; w1b[tid] = W1[256 + tid];
    b1v[tid] = b1[tid]; b2v[tid] = b2[tid]; b3v[tid] = b3[tid];
    w4s[tid] = W4[tid]; w4s[tid + 256] = W4[tid + 256]; w4s[tid + 512] = W4[tid + 512];
    if (tid < 2) {
        const uint32_t m = OFF_MB + tid * 32;
        MBAR_INIT(smb + m, 1);      MBAR_INIT(smb + m + 8, 1);       // F0, F1
        MBAR_INIT(smb + m + 16, 4); MBAR_INIT(smb + m + 24, 4);      // U0, U1
    }
    if (tid == 2) { MBAR_INIT(smb + OFF_TOK(0), 4); MBAR_INIT(smb + OFF_TOK(1), 4); }
    __syncthreads();
    if (tid < 4) MBAR_ARRIVE(smb + OFF_TOK(0));   // grant G0 the first MMA turn
    __syncthreads();

    const int bid = blockIdx.x, grid = gridDim.x;
    const int step = 2 * grid;
    const int t0A = bid * 2, t0B = bid * 2 + 1;
    const int ntA = (t0A < NTILES) ? ((NTILES - 1 - t0A) / step + 1) : 0;
    const int ntB = (t0B < NTILES) ? ((NTILES - 1 - t0B) / step + 1) : 0;
    const int t0 = gid ? t0B : t0A;
    const int total_chunks = (gid ? ntB : ntA) * 16;
    int g = 0;
    if (gtid == 0 && total_chunks > 0) {
        issue_load(smb, ring, mb, 0);
        if (total_chunks > 1) issue_load(smb, ring, mb, 1);
    }

    const float2* x2 = (const float2*)x;
    const int px = gtid >> 1, q = gtid & 1;
    int pcnt = 0;                              // MMA-phase counter (token parity)

    for (int t = t0; t < NTILES; t += step) {
        const int b = t >> 8;                 // 256 tiles per batch
        const int p0 = t * 64;
        const int sidx = __ldg(&sample_idx[b]);
        const float dyv = __ldg(&shiftv[sidx * 2]), dxv = __ldg(&shiftv[sidx * 2 + 1]);
        float sv, cvv;
        sincosf(__ldg(&rotang[sidx]), &sv, &cvv);

        // ---- layer 1 (SIMT) -> group A: 2 threads per pixel, 128 n each ----
        {
            float2 xv = x2[p0 + px];
            const float c0 = cvv * xv.x - sv * xv.y + dxv;
            const float c1 = sv * xv.x + cvv * xv.y + dyv;
#pragma unroll
            for (int i = 0; i < 64; i++) {
                const int n = q * 128 + i * 2;
                float h0 = fmaxf(fmaf(c0, w1a[n],     fmaf(c1, w1b[n],     b1v[n])),     0.f);
                float h1 = fmaxf(fmaf(c0, w1a[n + 1], fmaf(c1, w1b[n + 1], b1v[n + 1])), 0.f);
                store_h2(sm, abase, px, n, h0, h1);
            }
            if (gtid == 127 && (t & 255) == 0) {
                out[OUT_PIX + b] = dxv;
                out[OUT_PIX + 16 + b] = dyv;
            }
        }
        GBAR(bar);

        float d[4][8][4];
        // ---- MMA phase: layer 2 (token-gated, strict alternation) ----
        mbar_wait(tokMine, (uint32_t)(pcnt & 1));
        ZERO_D(d);
        run_layer(d, smb, ring, abase, mb, n0, lane, gtid, g, total_chunks);
        if (lane == 0) MBAR_ARRIVE(tokOther);
        pcnt++;
        GBAR(bar);                            // all MMA2 A-reads done before epi2 A-writes
        epi_store(sm, abase, d, b2v, n0, qm, qn);
        GBAR(bar);                            // A(=h2) complete before MMA3 reads

        // ---- MMA phase: layer 3 ----
        mbar_wait(tokMine, (uint32_t)(pcnt & 1));
        ZERO_D(d);
        run_layer(d, smb, ring, abase, mb, n0, lane, gtid, g, total_chunks);
        if (lane == 0) MBAR_ARRIVE(tokOther);
        pcnt++;
        epi3_fuse(d, b3v, w4s, part, n0, gwid, lane, qm, qn);
        GBAR(bar);                            // part complete before reduce

        // ---- final reduce: 4 n-group partials + bias + color affine ----
        for (int it = gtid; it < 192; it += 128) {
            const int pxr = it / 3, j = it - 3 * pxr;
            float o = part[pxr * 3 + j] + part[192 + pxr * 3 + j] +
                      part[384 + pxr * 3 + j] + part[576 + pxr * 3 + j] + __ldg(&b4[j]);
            if (sidx != 0)
                o = fmaf(o, __ldg(&cscal[sidx * 3 + j]), __ldg(&cshft[sidx * 3 + j]));
            out[(p0 + pxr) * 3 + j] = o;
        }
        // no trailing barrier: next tile's post-layer-1 GBAR orders reduce-vs-epi3
        // on part, and A's last readers (MMA3) finished before the pre-reduce GBAR.
    }

    // ---- end-of-stream token balance ----
    // G0 needs 2*ntA completions of TOK(0): 1 pre-arrival + G1's 2*ntB -> G1
    // covers any deficit. (G1 needs 2*ntB of TOK(1); G0 supplies 2*ntA >= 2*ntB.)
    if (gid == 1) {
        const int deficit = 2 * ntA - 1 - 2 * ntB;
        for (int i = 0; i < deficit; i++)
            if (lane == 0) MBAR_ARRIVE(smb + OFF_TOK(0));
    }
}

extern "C" void kernel_launch(void* const* d_in, const int* in_sizes, int n_in,
                              void* d_out, int out_size)
{
    (void)in_sizes; (void)n_in; (void)out_size;
    const float* x      = (const float*)d_in[0];
    const int*   sidx   = (const int*)  d_in[1];
    const float* shiftv = (const float*)d_in[2];
    const float* rotang = (const float*)d_in[3];
    const float* cscal  = (const float*)d_in[4];
    const float* cshft  = (const float*)d_in[5];
    const float* W1 = (const float*)d_in[6];
    const float* b1 = (const float*)d_in[7];
    const float* W2 = (const float*)d_in[8];
    const float* b2 = (const float*)d_in[9];
    const float* W3 = (const float*)d_in[10];
    const float* b3 = (const float*)d_in[11];
    const float* W4 = (const float*)d_in[12];
    const float* b4 = (const float*)d_in[13];
    float* out = (float*)d_out;

    int nsm = 0;
    cudaDeviceGetAttribute(&nsm, cudaDevAttrMultiProcessorCount, 0);
    if (nsm <= 0) nsm = 148;
    if (nsm * 2 > NTILES) nsm = NTILES / 2;

    prep_kernel<<<512, 256>>>(W2, W3);

    cudaFuncSetAttribute(inr_hmma_kernel,
                         cudaFuncAttributeMaxDynamicSharedMemorySize, SMEM_ALLOC);
    inr_hmma_kernel<<<nsm, NTHR, SMEM_ALLOC>>>(
        x, sidx, shiftv, rotang, cscal, cshft, W1, b1, b2, b3, W4, b4, out);
}

// round 17
// speedup vs baseline: 1.1479x; 1.1479x over previous
#include <cuda_runtime.h>
#include <cuda_fp16.h>
#include <cstdint>
#include <math.h>

#define NTHR 256
#define NTILES 2048                  // 128 pixels per tile
#define OUT_PIX (16*128*128*3)

// ---- smem byte offsets ----
#define OFF_STAGE(s) ((s)*20480)     // 2 stages: W, 20480 each
#define OFF_A   40960                // A: [128 m][256 k] fp16, 512B rows, XOR-swizzled 16B chunks
#define OFF_W1A 106496
#define OFF_W1B 107520
#define OFF_B1  108544
#define OFF_B2  109568
#define OFF_B3  110592
#define OFF_W4  111616               // float[768]
#define OFF_PART 114688              // float[4][128][3] layer-4 partials (6144 B)
#define OFF_MB  120832               // F0,F1,U0,U1
#define MB_F(s) (OFF_MB + (s)*8)
#define MB_U(s) (OFF_MB + 16 + (s)*8)
#define SMEM_ALLOC 120960

// fp16 weight images: [layer][kchunk(8 x k32)][256 n x 80B rows]
__device__ __align__(16) unsigned char g_W[2][8][20480];

// ---- helpers ----
__device__ __forceinline__ uint32_t smem_u32(const void* p) {
    uint32_t a;
    asm("{ .reg .u64 t; cvta.to.shared.u64 t, %1; cvt.u32.u64 %0, t; }" : "=r"(a) : "l"(p));
    return a;
}
#define MBAR_INIT(mbar, cnt) \
    asm volatile("mbarrier.init.shared.b64 [%0], %1;" :: "r"((uint32_t)(mbar)), "r"((uint32_t)(cnt)) : "memory")
#define MBAR_EXPECT_TX(mbar, tx) \
    asm volatile("mbarrier.arrive.expect_tx.shared.b64 _, [%0], %1;" :: "r"((uint32_t)(mbar)), "r"((uint32_t)(tx)) : "memory")
#define MBAR_ARRIVE(mbar) \
    asm volatile("mbarrier.arrive.shared.b64 _, [%0];" :: "r"((uint32_t)(mbar)) : "memory")

__device__ __forceinline__ void mbar_wait(uint32_t mbar, uint32_t parity) {
    uint32_t done;
    asm volatile("{\n\t.reg .pred p;\n\t"
                 "mbarrier.try_wait.parity.acquire.cta.shared::cta.b64 p, [%1], %2;\n\t"
                 "selp.b32 %0, 1, 0, p;\n\t}" : "=r"(done) : "r"(mbar), "r"(parity) : "memory");
    if (!done) {
        asm volatile("{\n\t.reg .pred P1;\n\t"
                     "W_%=:\n\t"
                     "mbarrier.try_wait.parity.acquire.cta.shared::cta.b64 P1, [%0], %1, 0x989680;\n\t"
                     "@P1 bra.uni D_%=;\n\t"
                     "bra.uni W_%=;\n\t"
                     "D_%=:\n\t}" :: "r"(mbar), "r"(parity) : "memory");
    }
}
__device__ __forceinline__ void bulk_ld(uint32_t dst, const void* src, uint32_t bytes, uint32_t mbar) {
    asm volatile("cp.async.bulk.shared::cluster.global.mbarrier::complete_tx::bytes [%0], [%1], %2, [%3];"
                 :: "r"(dst), "l"(src), "r"(bytes), "r"(mbar) : "memory");
}
#define LDSM4(r, addr) \
    asm volatile("ldmatrix.sync.aligned.m8n8.x4.shared.b16 {%0,%1,%2,%3}, [%4];" \
        : "=r"((r)[0]), "=r"((r)[1]), "=r"((r)[2]), "=r"((r)[3]) : "r"(addr))
#define MMA4(dd, a, b0_, b1_) \
    asm volatile("mma.sync.aligned.m16n8k16.row.col.f32.f16.f16.f32 " \
        "{%0,%1,%2,%3}, {%4,%5,%6,%7}, {%8,%9}, {%0,%1,%2,%3};" \
        : "+f"((dd)[0]), "+f"((dd)[1]), "+f"((dd)[2]), "+f"((dd)[3]) \
        : "r"((a)[0]), "r"((a)[1]), "r"((a)[2]), "r"((a)[3]), "r"(b0_), "r"(b1_))

// A smem address: [m][k] fp16, 512B rows, physical 16B chunk = (k/8) ^ (m&7)
__device__ __forceinline__ uint32_t a_addr(uint32_t base, int m, int k) {
    return base + (uint32_t)(m * 512) +
           (uint32_t)(((((k >> 3) ^ (m & 7))) << 4) + ((k & 7) << 1));
}
__device__ __forceinline__ void store_h2(unsigned char* sm, int m, int n, float v0, float v1) {
    *(__half2*)(sm + a_addr(OFF_A, m, n)) = __float22half2_rn(make_float2(v0, v1));
}

// ---- prep: W2/W3 fp16 images, [n][k] layout, 80B rows ----
__global__ void prep_kernel(const float* __restrict__ W2, const float* __restrict__ W3) {
    int idx = blockIdx.x * blockDim.x + threadIdx.x;   // 0..131071
    int l = idx >> 16, r = idx & 65535;
    int k = r >> 8, n = r & 255;
    float w = (l ? W3 : W2)[k * 256 + n];
    __half h = __float2half_rn(w);
    int kc = k >> 5, kk = k & 31;
    *(__half*)&g_W[l][kc][n * 80 + kk * 2] = h;
}

__device__ __forceinline__ void issue_load(uint32_t smb, int g) {
    const int lc = g & 15;                    // 16 chunks per tile (8 per layer x 2 layers)
    const int l = lc >> 3, kc = lc & 7, s = g & 1;
    const uint32_t mb = smb + MB_F(s);
    MBAR_EXPECT_TX(mb, 20480);
    bulk_ld(smb + OFF_STAGE(s), &g_W[l][kc][0], 20480, mb);
}

// init accumulators with the layer bias (bias enters fp32 accumulation first)
__device__ __forceinline__ void init_d_bias(
    float (&d)[4][8][4], const float* bias, int n0, int qn)
{
#pragma unroll
    for (int nt = 0; nt < 8; nt++) {
        const float2 bb = *(const float2*)&bias[n0 + nt * 8 + qn];
#pragma unroll
        for (int mt = 0; mt < 4; mt++) {
            d[mt][nt][0] = bb.x;
            d[mt][nt][1] = bb.y;
            d[mt][nt][2] = bb.x;
            d[mt][nt][3] = bb.y;
        }
    }
}

// one 256->256 layer for 128 pixels: 8 warps, warp tile 64x64, pure fp16 HMMA
__device__ __forceinline__ void run_layer(
    float (&d)[4][8][4], uint32_t smb, int m0, int n0,
    int lane, int tid, int& g, int total_chunks)
{
    const int aRow = (lane & 7) + ((lane >> 3) & 1) * 8;   // ldmatrix A row-in-tile
    const int aCs  = lane >> 4;                            // A k8-chunk select
    const int wRow = ((lane >> 4) & 1) * 8 + (lane & 7);   // ldmatrix B row (n)
    const int wCs  = (lane >> 3) & 1;                      // B k8-chunk select

    for (int kc = 0; kc < 8; kc++) {
        const int s = g & 1;
        const uint32_t ph = (uint32_t)((g >> 1) & 1);
        mbar_wait(smb + MB_F(s), ph);
        const uint32_t stH = smb + OFF_STAGE(s);
#pragma unroll
        for (int ks = 0; ks < 2; ks++) {
            const int cb = kc * 4 + ks * 2 + aCs;          // A 16B-chunk index
            uint32_t ah[4][4];
#pragma unroll
            for (int mt = 0; mt < 4; mt++) {
                const int mA = m0 + mt * 16 + aRow;
                const uint32_t co = (uint32_t)((cb ^ (mA & 7)) << 4);
                LDSM4(ah[mt], smb + OFF_A + (uint32_t)(mA * 512) + co);
            }
            const uint32_t wko = (uint32_t)((ks * 2 + wCs) << 4);
#pragma unroll
            for (int np = 0; np < 4; np++) {
                const uint32_t wro = (uint32_t)((n0 + np * 16 + wRow) * 80) + wko;
                uint32_t wh[4];
                LDSM4(wh, stH + wro);
#pragma unroll
                for (int mt = 0; mt < 4; mt++) {
                    MMA4(d[mt][np*2],   ah[mt], wh[0], wh[1]);
                    MMA4(d[mt][np*2+1], ah[mt], wh[2], wh[3]);
                }
            }
        }
        if (lane == 0) MBAR_ARRIVE(smb + MB_U(s));         // per-warp arrive (count 8)
        if (tid == 0 && g + 2 < total_chunks) {
            mbar_wait(smb + MB_U(s), ph);                  // stage fully consumed
            issue_load(smb, g + 2);
        }
        g++;
    }
}

// layer-2 epilogue: relu + pack only (bias already in d)
__device__ __forceinline__ void epi_store(
    unsigned char* sm, float (&d)[4][8][4], int m0, int n0, int qm, int qn)
{
#pragma unroll
    for (int mt = 0; mt < 4; mt++) {
        const int mA = m0 + mt * 16 + qm;
#pragma unroll
        for (int nt = 0; nt < 8; nt++) {
            const int n = n0 + nt * 8 + qn;
            store_h2(sm, mA,     n, fmaxf(d[mt][nt][0], 0.f), fmaxf(d[mt][nt][1], 0.f));
            store_h2(sm, mA + 8, n, fmaxf(d[mt][nt][2], 0.f), fmaxf(d[mt][nt][3], 0.f));
        }
    }
}

// layer-3 epilogue fused with layer-4 (bias already in d): relu(d)·W4
__device__ __forceinline__ void epi3_fuse(
    float (&d)[4][8][4], const float* w4s, float* part,
    int m0, int n0, int wid, int lane, int qm, int qn)
{
    const int n0g = wid >> 1;
#pragma unroll
    for (int mt = 0; mt < 4; mt++) {
        float oo[2][3];
#pragma unroll
        for (int h = 0; h < 2; h++)
#pragma unroll
            for (int j = 0; j < 3; j++) oo[h][j] = 0.f;
#pragma unroll
        for (int nt = 0; nt < 8; nt++) {
            const int n = n0 + nt * 8 + qn;
            const float2 wA = *(const float2*)&w4s[n * 3];
            const float2 wB = *(const float2*)&w4s[n * 3 + 2];
            const float2 wC = *(const float2*)&w4s[n * 3 + 4];
            float v0 = fmaxf(d[mt][nt][0], 0.f);
            float v1 = fmaxf(d[mt][nt][1], 0.f);
            float v2 = fmaxf(d[mt][nt][2], 0.f);
            float v3 = fmaxf(d[mt][nt][3], 0.f);
            oo[0][0] = fmaf(v0, wA.x, fmaf(v1, wB.y, oo[0][0]));
            oo[0][1] = fmaf(v0, wA.y, fmaf(v1, wC.x, oo[0][1]));
            oo[0][2] = fmaf(v0, wB.x, fmaf(v1, wC.y, oo[0][2]));
            oo[1][0] = fmaf(v2, wA.x, fmaf(v3, wB.y, oo[1][0]));
            oo[1][1] = fmaf(v2, wA.y, fmaf(v3, wC.x, oo[1][1]));
            oo[1][2] = fmaf(v2, wB.x, fmaf(v3, wC.y, oo[1][2]));
        }
#pragma unroll
        for (int h = 0; h < 2; h++)
#pragma unroll
            for (int j = 0; j < 3; j++) {
                float v = oo[h][j];
                v += __shfl_xor_sync(0xFFFFFFFFu, v, 1);
                v += __shfl_xor_sync(0xFFFFFFFFu, v, 2);
                oo[h][j] = v;
            }
        if ((lane & 3) == 0) {
#pragma unroll
            for (int h = 0; h < 2; h++) {
                const int row = m0 + mt * 16 + h * 8 + qm;
#pragma unroll
                for (int j = 0; j < 3; j++)
                    part[n0g * 384 + row * 3 + j] = oo[h][j];
            }
        }
    }
}

__global__ void __launch_bounds__(NTHR, 1) inr_hmma_kernel(
    const float* __restrict__ x, const int* __restrict__ sample_idx,
    const float* __restrict__ shiftv, const float* __restrict__ rotang,
    const float* __restrict__ cscal, const float* __restrict__ cshft,
    const float* __restrict__ W1, const float* __restrict__ b1,
    const float* __restrict__ b2, const float* __restrict__ b3,
    const float* __restrict__ W4, const float* __restrict__ b4,
    float* __restrict__ out)
{
    extern __shared__ __align__(128) unsigned char sm[];
    const uint32_t smb = smem_u32(sm);

    const int tid = threadIdx.x;
    const int lane = tid & 31, wid = tid >> 5;
    const int m0 = (wid & 1) * 64, n0 = (wid >> 1) * 64;    // warp tile 64x64
    const int qm = lane >> 2, qn = (lane & 3) * 2;

    float* w1a = (float*)(sm + OFF_W1A);
    float* w1b = (float*)(sm + OFF_W1B);
    float* b1v = (float*)(sm + OFF_B1);
    float* b2v = (float*)(sm + OFF_B2);
    float* b3v = (float*)(sm + OFF_B3);
    float* w4s = (float*)(sm + OFF_W4);
    float* part = (float*)(sm + OFF_PART);

    w1a[tid] = W1[tid]; w1b[tid] = W1[256 + tid];
    b1v[tid] = b1[tid]; b2v[tid] = b2[tid]; b3v[tid] = b3[tid];
    w4s[tid] = W4[tid]; w4s[tid + 256] = W4[tid + 256]; w4s[tid + 512] = W4[tid + 512];
    if (tid == 0) {
        MBAR_INIT(smb + MB_F(0), 1); MBAR_INIT(smb + MB_F(1), 1);
        MBAR_INIT(smb + MB_U(0), 8); MBAR_INIT(smb + MB_U(1), 8);
    }
    __syncthreads();

    const int bid = blockIdx.x, grid = gridDim.x;
    const int ntiles = (NTILES - 1 - bid) / grid + 1;
    const int total_chunks = ntiles * 16;
    int g = 0;
    if (tid == 0) { issue_load(smb, 0); issue_load(smb, 1); }

    const float2* x2 = (const float2*)x;

    for (int t = bid; t < NTILES; t += grid) {
        const int b = t >> 7;                 // 128 tiles per batch
        const int p0 = t * 128;
        const int sidx = sample_idx[b];
        const float dyv = shiftv[sidx * 2], dxv = shiftv[sidx * 2 + 1];
        float sv, cvv;
        sincosf(rotang[sidx], &sv, &cvv);

        // ---- layer 1 (SIMT, float4 weight reads) -> A fp16 smem ----
        {
            const int px = tid >> 1, q = tid & 1;
            float2 xv = x2[p0 + px];
            const float c0 = cvv * xv.x - sv * xv.y + dxv;
            const float c1 = sv * xv.x + cvv * xv.y + dyv;
#pragma unroll
            for (int i = 0; i < 32; i++) {
                const int n = q * 128 + i * 4;
                const float4 wa = *(const float4*)&w1a[n];
                const float4 wb = *(const float4*)&w1b[n];
                const float4 bv = *(const float4*)&b1v[n];
                float h0 = fmaxf(fmaf(c0, wa.x, fmaf(c1, wb.x, bv.x)), 0.f);
                float h1 = fmaxf(fmaf(c0, wa.y, fmaf(c1, wb.y, bv.y)), 0.f);
                float h2 = fmaxf(fmaf(c0, wa.z, fmaf(c1, wb.z, bv.z)), 0.f);
                float h3 = fmaxf(fmaf(c0, wa.w, fmaf(c1, wb.w, bv.w)), 0.f);
                store_h2(sm, px, n,     h0, h1);
                store_h2(sm, px, n + 2, h2, h3);
            }
            if (tid == 255 && (t & 127) == 0) {
                out[OUT_PIX + b] = dxv;
                out[OUT_PIX + 16 + b] = dyv;
            }
        }
        __syncthreads();

        float d[4][8][4];
        init_d_bias(d, b2v, n0, qn);
        run_layer(d, smb, m0, n0, lane, tid, g, total_chunks);   // layer 2 (+b2)
        __syncthreads();
        epi_store(sm, d, m0, n0, qm, qn);
        __syncthreads();

        init_d_bias(d, b3v, n0, qn);
        run_layer(d, smb, m0, n0, lane, tid, g, total_chunks);   // layer 3 (+b3)
        epi3_fuse(d, w4s, part, m0, n0, wid, lane, qm, qn);      // fused layer 4 partials
        __syncthreads();

        // ---- final reduce: 4 n0-group partials + bias + color affine ----
        for (int it = tid; it < 384; it += NTHR) {
            const int px = it / 3, j = it - 3 * px;
            float o = part[px * 3 + j] + part[384 + px * 3 + j] +
                      part[768 + px * 3 + j] + part[1152 + px * 3 + j] + b4[j];
            if (sidx != 0)
                o = fmaf(o, cscal[sidx * 3 + j], cshft[sidx * 3 + j]);
            out[(p0 + px) * 3 + j] = o;
        }
    }
}

extern "C" void kernel_launch(void* const* d_in, const int* in_sizes, int n_in,
                              void* d_out, int out_size)
{
    (void)in_sizes; (void)n_in; (void)out_size;
    const float* x      = (const float*)d_in[0];
    const int*   sidx   = (const int*)  d_in[1];
    const float* shiftv = (const float*)d_in[2];
    const float* rotang = (const float*)d_in[3];
    const float* cscal  = (const float*)d_in[4];
    const float* cshft  = (const float*)d_in[5];
    const float* W1 = (const float*)d_in[6];
    const float* b1 = (const float*)d_in[7];
    const float* W2 = (const float*)d_in[8];
    const float* b2 = (const float*)d_in[9];
    const float* W3 = (const float*)d_in[10];
    const float* b3 = (const float*)d_in[11];
    const float* W4 = (const float*)d_in[12];
    const float* b4 = (const float*)d_in[13];
    float* out = (float*)d_out;

    int nsm = 0;
    cudaDeviceGetAttribute(&nsm, cudaDevAttrMultiProcessorCount, 0);
    if (nsm <= 0) nsm = 148;
    if (nsm > NTILES) nsm = NTILES;

    prep_kernel<<<512, 256>>>(W2, W3);

    cudaFuncSetAttribute(inr_hmma_kernel,
                         cudaFuncAttributeMaxDynamicSharedMemorySize, SMEM_ALLOC);
    inr_hmma_kernel<<<nsm, NTHR, SMEM_ALLOC>>>(
        x, sidx, shiftv, rotang, cscal, cshft, W1, b1, b2, b3, W4, b4, out);
}